// round 3
// baseline (speedup 1.0000x reference)
#include <cuda_runtime.h>
#include <cuda_bf16.h>

// Problem constants
#define BB 4
#define TT 2048
#define NE 32
#define NH 8
#define HD 4
#define NB (TT / 4)               // 512 4-row blocks per (b,h)

#define NSLICE 32                 // xpart slices per batch (64 rows each)
#define ROWS_B 16                 // kernel B rows per CTA
#define NCTA_B ((BB * TT) / ROWS_B)  // 512

// Partial sums: g_xpart[b][slice][c*32+e] = sum over slice rows (row%4==c) of x[row][e]
__device__ float g_xpart[BB][NSLICE][128];
// Fused table: g_G[b][h*4+c][o'] = sum_d Vbar[b][c][h*4+d] * Wp[o', h*4+d]
__device__ float g_G[BB][NE][NE];

__device__ __forceinline__ float clip100(float v) {
    return fminf(fmaxf(v, -100.0f), 100.0f);
}

// -------- Kernel A1: partial column sums of x, bucketed by (row % 4) --------
// grid = BB*NSLICE = 128, 128 threads; each CTA covers 64 consecutive rows.
__global__ __launch_bounds__(128) void xpart_kernel(const float* __restrict__ x)
{
    const int b   = blockIdx.x >> 5;
    const int s   = blockIdx.x & 31;
    const int tid = threadIdx.x;

    const float* xs0 = x + ((size_t)b * TT + (size_t)s * 64) * NE;
    float acc = 0.0f;
    #pragma unroll
    for (int j = 0; j < 16; ++j) acc += xs0[j * 128 + tid];
    g_xpart[b][s][tid] = acc;
}

// -------- Kernel A2: finish Vbar, fold Wp -> G --------
// grid = BB, 128 threads.
__global__ __launch_bounds__(128) void gtab_kernel(
    const float* __restrict__ Wv, const float* __restrict__ bv,
    const float* __restrict__ Wp)
{
    const int b   = blockIdx.x;
    const int tid = threadIdx.x;

    __shared__ float sXbar[4][NE];
    __shared__ float sVb[4][NE];

    // xbar[c][e], c = tid>>5, e = tid&31
    float xs = 0.0f;
    #pragma unroll
    for (int s = 0; s < NSLICE; ++s) xs += g_xpart[b][s][tid];
    sXbar[tid >> 5][tid & 31] = xs * (1.0f / (float)NB);
    __syncthreads();

    // Vbar[c][o] = bv[o] + xbar[c] . Wv[o,:]
    {
        const int c = tid >> 5, o = tid & 31;
        float acc = bv[o];
        #pragma unroll
        for (int e = 0; e < NE; ++e) acc += sXbar[c][e] * Wv[o * NE + e];
        sVb[c][o] = acc;
    }
    __syncthreads();

    // G[h*4+c][o'] = sum_d Vbar[c][h*4+d] * Wp[o', h*4+d]
    #pragma unroll
    for (int i = 0; i < 8; ++i) {
        const int g  = i * 128 + tid;      // 0..1023
        const int hc = g >> 5;             // h*4+c
        const int op = g & 31;
        const int h  = hc >> 2;
        const int c  = hc & 3;
        float acc = 0.0f;
        #pragma unroll
        for (int d = 0; d < HD; ++d)
            acc += sVb[c][h * 4 + d] * Wp[op * NE + h * 4 + d];
        g_G[b][hc][op] = acc;
    }
}

// -------- Kernel B: q, RXTX, softmax -> P, z = bp + P.G --------
// 128 threads = 16 rows x 8 parts; part p == head p. p = tid&7, r = tid>>3.
__global__ __launch_bounds__(128) void rxtx_attn_kernel(
    const float* __restrict__ x,
    const float* __restrict__ Wq, const float* __restrict__ bq,
    const float* __restrict__ bp,
    float* __restrict__ out)
{
    __shared__ float sWq[NE][NE];
    __shared__ float sG[NE][33];
    __shared__ float sbq[NE];
    __shared__ float sbp[NE];
    __shared__ float sX[ROWS_B][33];     // x rows, later reused as output staging
    __shared__ float sQ[ROWS_B][33];
    __shared__ float sP[ROWS_B][33];

    const int tid = threadIdx.x;
    const int p   = tid & 7;             // head
    const int r   = tid >> 3;            // row within CTA (0..15)
    const int tg0 = blockIdx.x * ROWS_B;
    const int b   = tg0 / TT;            // 128 CTAs per batch, aligned

    // ---- stage Wq, G, biases, x (all coalesced) ----
    #pragma unroll
    for (int i = 0; i < 8; ++i) {
        const int idx = i * 128 + tid;
        sWq[idx >> 5][idx & 31] = Wq[idx];
        sG[idx >> 5][idx & 31]  = g_G[b][idx >> 5][idx & 31];
    }
    if (tid < NE)            sbq[tid]      = bq[tid];
    else if (tid < 2 * NE)   sbp[tid - NE] = bp[tid - NE];

    const float* xblk = x + (size_t)tg0 * NE;
    #pragma unroll
    for (int i = 0; i < 4; ++i) {
        const int idx = i * 128 + tid;
        sX[idx >> 5][idx & 31] = xblk[idx];
    }
    __syncthreads();

    // ---- q: thread computes cols [4p, 4p+4) of row r ----
    float xr[NE];
    #pragma unroll
    for (int e = 0; e < NE; ++e) xr[e] = sX[r][e];
    const int o0 = p * 4;
    #pragma unroll
    for (int i = 0; i < 4; ++i) {
        const int o = o0 + i;
        float a = sbq[o];
        #pragma unroll
        for (int e = 0; e < NE; ++e) a += xr[e] * sWq[o][e];
        sQ[r][o] = clip100(a);
    }
    __syncthreads();

    // ---- RXTX for (block of r, head p), row rr; 4-way softmax ----
    {
        const int blk = r & ~3;
        const int rr  = r & 3;
        const int hc  = o0;

        const float X1  = sQ[blk + 0][hc + 0], X2  = sQ[blk + 0][hc + 1],
                    X3  = sQ[blk + 0][hc + 2], X4  = sQ[blk + 0][hc + 3];
        const float X5  = sQ[blk + 1][hc + 0], X6  = sQ[blk + 1][hc + 1],
                    X7  = sQ[blk + 1][hc + 2], X8  = sQ[blk + 1][hc + 3];
        const float X9  = sQ[blk + 2][hc + 0], X10 = sQ[blk + 2][hc + 1],
                    X11 = sQ[blk + 2][hc + 2], X12 = sQ[blk + 2][hc + 3];
        const float X13 = sQ[blk + 3][hc + 0], X14 = sQ[blk + 3][hc + 1],
                    X15 = sQ[blk + 3][hc + 2], X16 = sQ[blk + 3][hc + 3];

        const float m1  = (-X2 + X3 - X4 + X8) * (X8 + X11);
        const float m2  = (X1 - X5 - X6 + X7) * (X15 + X5);
        const float m3  = (-X2 + X12) * (-X10 + X16 + X12);
        const float m4  = (X9 - X6) * (X13 + X9 - X14);
        const float m5  = (X2 + X11) * (-X6 + X15 - X7);
        const float m6  = (X6 + X11) * (X6 + X7 - X11);
        const float m7  = X11 * (X6 + X7);
        const float m8  = X2 * (-X14 - X10 + X6 - X15 + X7 + X16 + X12);
        const float m9  = X6 * (X13 + X9 - X14 - X10 + X6 + X7 - X11);
        const float m10 = (X2 - X3 + X7 + X11 + X4 - X8) * X11;
        const float m11 = (X5 + X6 - X7) * X5;
        const float m12 = (X2 - X3 + X4) * X8;
        const float m13 = (-X1 + X5 + X6 + X3 - X7 + X11) * X15;
        const float m14 = (-X1 + X5 + X6) * (X13 + X9 + X15);
        const float m15 = (X2 + X4 - X8) * (X11 + X16 + X12);
        const float m16 = (X1 - X8) * (X9 - X16);
        const float m17 = X12 * (X10 - X12);
        const float m18 = X9 * (X13 - X14);
        const float m19 = (-X2 + X3) * (-X15 + X7 + X8);
        const float m20 = (X5 + X9 - X8) * X9;
        const float m21 = X8 * (X9 - X8 + X12);
        const float m22 = (-X6 + X7) * (X5 + X7 - X11);
        const float m23 = X1 * (X13 - X5 + X16);
        const float m24 = (-X1 + X4 + X12) * X16;
        const float m25 = (X9 + X2 + X10) * X14;
        const float m26 = (X6 + X10 + X12) * X10;

        const float z1 = m7 - m11 - m12;
        const float z2 = m1 + m12 + m21;
        const float z3 = m3 + m17 - m24;
        const float z4 = m2 + m11 + m23;
        const float z5 = m5 + m7 + m8;
        const float z6 = m4 - m18 - m20;
        const float z7 = m6 - m7 - m9;
        const float z8 = m17 + m18;

        const float c01 = m2 - m5 - z1 + m13 + m19;
        const float c02 = z2 + z3 + m15 + m16;
        const float c03 = z4 - z3 - z5 - m13;
        const float c11 = m1 + m6 - z1 + m10 + m22;
        const float c12 = z2 - z6 + z7 + m10;
        const float c13 = z4 + z6 + m14 + m16;
        const float c22 = m4 - z7 - z8 + m26;
        const float c23 = m3 + z5 + z8 + m25;

        float a0, a1, a2, a3;
        if      (rr == 0) { a0 = 0.0f; a1 = c01;  a2 = c02;  a3 = c03;  }
        else if (rr == 1) { a0 = c01;  a1 = c11;  a2 = c12;  a3 = c13;  }
        else if (rr == 2) { a0 = c02;  a1 = c12;  a2 = c22;  a3 = c23;  }
        else              { a0 = c03;  a1 = c13;  a2 = c23;  a3 = 0.0f; }

        a0 = clip100(a0) * 0.5f;
        a1 = clip100(a1) * 0.5f;
        a2 = clip100(a2) * 0.5f;
        a3 = clip100(a3) * 0.5f;

        const float mx = fmaxf(fmaxf(a0, a1), fmaxf(a2, a3));
        const float e0 = __expf(a0 - mx);
        const float e1 = __expf(a1 - mx);
        const float e2 = __expf(a2 - mx);
        const float e3 = __expf(a3 - mx);
        const float inv = 1.0f / (e0 + e1 + e2 + e3);

        sP[r][hc + 0] = e0 * inv;
        sP[r][hc + 1] = e1 * inv;
        sP[r][hc + 2] = e2 * inv;
        sP[r][hc + 3] = e3 * inv;
    }
    __syncthreads();

    // ---- z[o'] = bp[o'] + sum_hc P[r][hc] * G[hc][o'], o' in [4p, 4p+4) ----
    float pr[NE];
    #pragma unroll
    for (int e = 0; e < NE; ++e) pr[e] = sP[r][e];
    #pragma unroll
    for (int i = 0; i < 4; ++i) {
        const int o = o0 + i;
        float a = sbp[o];
        #pragma unroll
        for (int e = 0; e < NE; ++e) a += pr[e] * sG[e][o];
        sX[r][o] = a;      // reuse sX: all reads of x completed in q phase
    }
    __syncthreads();

    // ---- coalesced store ----
    float* ob = out + (size_t)tg0 * NE;
    #pragma unroll
    for (int i = 0; i < 4; ++i) {
        const int idx = i * 128 + tid;
        ob[idx] = sX[idx >> 5][idx & 31];
    }
}

extern "C" void kernel_launch(void* const* d_in, const int* in_sizes, int n_in,
                              void* d_out, int out_size)
{
    // metadata order: x, Wq, bq, Wk, bk, Wv, bv, Wp, bp   (Wk/bk are dead code)
    const float* x  = (const float*)d_in[0];
    const float* Wq = (const float*)d_in[1];
    const float* bq = (const float*)d_in[2];
    const float* Wv = (const float*)d_in[5];
    const float* bv = (const float*)d_in[6];
    const float* Wp = (const float*)d_in[7];
    const float* bp = (const float*)d_in[8];
    float* out = (float*)d_out;

    xpart_kernel<<<BB * NSLICE, 128>>>(x);
    gtab_kernel<<<BB, 128>>>(Wv, bv, Wp);
    rxtx_attn_kernel<<<NCTA_B, 128>>>(x, Wq, bq, bp, out);
}

// round 4
// speedup vs baseline: 2.2751x; 2.2751x over previous
#include <cuda_runtime.h>
#include <cuda_bf16.h>

// Problem constants
#define BB 4
#define TT 2048
#define NE 32
#define NH 8
#define HD 4
#define NB (TT / 4)                 // 512 4-row blocks per (b,h)

#define NSLICE 64                   // xpart slices per batch (32 rows each)
#define ROWS_B 32                   // kernel B rows per CTA
#define THR_B 256                   // 8 warps: warp = head, lane = row
#define NCTA_B ((BB * TT) / ROWS_B) // 256

// g_xpart[b][s][c*32+e] = sum over slice-s rows with (row%4==c) of x[row][e]
__device__ float g_xpart[BB][NSLICE][128];

__device__ __forceinline__ float clip100(float v) {
    return fminf(fmaxf(v, -100.0f), 100.0f);
}

// -------- Kernel A: partial column sums of x, bucketed by (row % 4) --------
// grid = BB*NSLICE = 256, 128 threads; each CTA covers 32 consecutive rows.
// idx = j*128+tid -> local row = j*4 + (tid>>5), so c = tid>>5 is constant.
__global__ __launch_bounds__(128) void xpart_kernel(const float* __restrict__ x)
{
    const int b   = blockIdx.x >> 6;
    const int s   = blockIdx.x & 63;
    const int tid = threadIdx.x;

    const float* xs0 = x + ((size_t)b * TT + (size_t)s * 32) * NE;
    float acc = 0.0f;
    #pragma unroll
    for (int j = 0; j < 8; ++j) acc += xs0[j * 128 + tid];
    g_xpart[b][s][tid] = acc;
}

// -------- Kernel B: fused Vbar/G + q, RXTX, softmax, z = bp + P.G --------
// 256 threads = 8 warps (w = head) x 32 lanes (l = row).
__global__ __launch_bounds__(THR_B) void rxtx_attn_kernel(
    const float* __restrict__ x,
    const float* __restrict__ Wq, const float* __restrict__ bq,
    const float* __restrict__ Wv, const float* __restrict__ bv,
    const float* __restrict__ Wp, const float* __restrict__ bp,
    float* __restrict__ out)
{
    __shared__ float sWq[NE][NE];       // broadcast reads only
    __shared__ float sWv[NE][33];       // per-lane row reads -> padded
    __shared__ float sWp[NE][33];
    __shared__ float sG[NE][33];
    __shared__ float sbq[NE];
    __shared__ float sbp[NE];
    __shared__ float sXh[2][128];       // xpart halves
    __shared__ float sVb[4][NE];
    __shared__ float sX[ROWS_B][33];    // x rows; reused as output staging
    __shared__ float sQ[ROWS_B][33];
    __shared__ float sP[ROWS_B][33];

    const int tid = threadIdx.x;
    const int w   = tid >> 5;           // warp = head
    const int l   = tid & 31;           // lane = row
    const int tg0 = blockIdx.x * ROWS_B;
    const int b   = tg0 >> 11;          // 64 CTAs per batch, aligned

    // ================= Phase 0: stage everything =================
    #pragma unroll
    for (int i = 0; i < 4; ++i) {
        const int idx = i * THR_B + tid;          // 0..1023
        const int ro = idx >> 5, co = idx & 31;
        sWq[ro][co] = Wq[idx];
        sWv[ro][co] = Wv[idx];
        sWp[ro][co] = Wp[idx];
    }
    if (tid < NE)          sbq[tid]      = bq[tid];
    else if (tid < 2 * NE) sbp[tid - NE] = bp[tid - NE];

    // finish half of the xpart reduction: thread (half, bucket)
    {
        const int half = tid >> 7;                // 0/1
        const int bkt  = tid & 127;
        float xs = 0.0f;
        #pragma unroll
        for (int s = 0; s < 32; ++s) xs += g_xpart[b][half * 32 + s][bkt];
        sXh[half][bkt] = xs;
    }

    // stage this CTA's 32 x-rows (coalesced)
    const float* xblk = x + (size_t)tg0 * NE;
    #pragma unroll
    for (int i = 0; i < 4; ++i) {
        const int idx = i * THR_B + tid;
        sX[idx >> 5][idx & 31] = xblk[idx];
    }
    __syncthreads();

    // ========== Phase 1: q matvec (all) + Vbar (tid<128) ==========
    const int o0 = w * 4;
    {
        float xr[NE];
        #pragma unroll
        for (int e = 0; e < NE; ++e) xr[e] = sX[l][e];
        #pragma unroll
        for (int i = 0; i < 4; ++i) {
            const int o = o0 + i;                 // warp-uniform
            float a = sbq[o];
            #pragma unroll
            for (int e = 0; e < NE; ++e) a += xr[e] * sWq[o][e];  // broadcast
            sQ[l][o] = clip100(a);
        }
    }
    if (tid < 128) {
        const int c = tid >> 5, o = tid & 31;
        const float inv_nb = 1.0f / (float)NB;
        float acc = bv[o];
        #pragma unroll
        for (int e = 0; e < NE; ++e) {
            const float xb = (sXh[0][c * 32 + e] + sXh[1][c * 32 + e]) * inv_nb;
            acc += xb * sWv[o][e];                // padded: conflict-free
        }
        sVb[c][o] = acc;
    }
    __syncthreads();

    // ========== Phase 2: RXTX + softmax (all) + G build (all) ==========
    {
        const int blk = l & ~3;
        const int rr  = l & 3;
        const int hc  = o0;

        const float X1  = sQ[blk + 0][hc + 0], X2  = sQ[blk + 0][hc + 1],
                    X3  = sQ[blk + 0][hc + 2], X4  = sQ[blk + 0][hc + 3];
        const float X5  = sQ[blk + 1][hc + 0], X6  = sQ[blk + 1][hc + 1],
                    X7  = sQ[blk + 1][hc + 2], X8  = sQ[blk + 1][hc + 3];
        const float X9  = sQ[blk + 2][hc + 0], X10 = sQ[blk + 2][hc + 1],
                    X11 = sQ[blk + 2][hc + 2], X12 = sQ[blk + 2][hc + 3];
        const float X13 = sQ[blk + 3][hc + 0], X14 = sQ[blk + 3][hc + 1],
                    X15 = sQ[blk + 3][hc + 2], X16 = sQ[blk + 3][hc + 3];

        const float m1  = (-X2 + X3 - X4 + X8) * (X8 + X11);
        const float m2  = (X1 - X5 - X6 + X7) * (X15 + X5);
        const float m3  = (-X2 + X12) * (-X10 + X16 + X12);
        const float m4  = (X9 - X6) * (X13 + X9 - X14);
        const float m5  = (X2 + X11) * (-X6 + X15 - X7);
        const float m6  = (X6 + X11) * (X6 + X7 - X11);
        const float m7  = X11 * (X6 + X7);
        const float m8  = X2 * (-X14 - X10 + X6 - X15 + X7 + X16 + X12);
        const float m9  = X6 * (X13 + X9 - X14 - X10 + X6 + X7 - X11);
        const float m10 = (X2 - X3 + X7 + X11 + X4 - X8) * X11;
        const float m11 = (X5 + X6 - X7) * X5;
        const float m12 = (X2 - X3 + X4) * X8;
        const float m13 = (-X1 + X5 + X6 + X3 - X7 + X11) * X15;
        const float m14 = (-X1 + X5 + X6) * (X13 + X9 + X15);
        const float m15 = (X2 + X4 - X8) * (X11 + X16 + X12);
        const float m16 = (X1 - X8) * (X9 - X16);
        const float m17 = X12 * (X10 - X12);
        const float m18 = X9 * (X13 - X14);
        const float m19 = (-X2 + X3) * (-X15 + X7 + X8);
        const float m20 = (X5 + X9 - X8) * X9;
        const float m21 = X8 * (X9 - X8 + X12);
        const float m22 = (-X6 + X7) * (X5 + X7 - X11);
        const float m23 = X1 * (X13 - X5 + X16);
        const float m24 = (-X1 + X4 + X12) * X16;
        const float m25 = (X9 + X2 + X10) * X14;
        const float m26 = (X6 + X10 + X12) * X10;

        const float z1 = m7 - m11 - m12;
        const float z2 = m1 + m12 + m21;
        const float z3 = m3 + m17 - m24;
        const float z4 = m2 + m11 + m23;
        const float z5 = m5 + m7 + m8;
        const float z6 = m4 - m18 - m20;
        const float z7 = m6 - m7 - m9;
        const float z8 = m17 + m18;

        const float c01 = m2 - m5 - z1 + m13 + m19;
        const float c02 = z2 + z3 + m15 + m16;
        const float c03 = z4 - z3 - z5 - m13;
        const float c11 = m1 + m6 - z1 + m10 + m22;
        const float c12 = z2 - z6 + z7 + m10;
        const float c13 = z4 + z6 + m14 + m16;
        const float c22 = m4 - z7 - z8 + m26;
        const float c23 = m3 + z5 + z8 + m25;

        float a0, a1, a2, a3;
        if      (rr == 0) { a0 = 0.0f; a1 = c01;  a2 = c02;  a3 = c03;  }
        else if (rr == 1) { a0 = c01;  a1 = c11;  a2 = c12;  a3 = c13;  }
        else if (rr == 2) { a0 = c02;  a1 = c12;  a2 = c22;  a3 = c23;  }
        else              { a0 = c03;  a1 = c13;  a2 = c23;  a3 = 0.0f; }

        a0 = clip100(a0) * 0.5f;
        a1 = clip100(a1) * 0.5f;
        a2 = clip100(a2) * 0.5f;
        a3 = clip100(a3) * 0.5f;

        const float mx = fmaxf(fmaxf(a0, a1), fmaxf(a2, a3));
        const float e0 = __expf(a0 - mx);
        const float e1 = __expf(a1 - mx);
        const float e2 = __expf(a2 - mx);
        const float e3 = __expf(a3 - mx);
        const float inv = 1.0f / (e0 + e1 + e2 + e3);

        sP[l][hc + 0] = e0 * inv;
        sP[l][hc + 1] = e1 * inv;
        sP[l][hc + 2] = e2 * inv;
        sP[l][hc + 3] = e3 * inv;
    }
    // G[hc][o'] = sum_d Vb[c][h*4+d] * Wp[o', h*4+d]; 4 entries per thread
    #pragma unroll
    for (int i = 0; i < 4; ++i) {
        const int g  = i * THR_B + tid;   // 0..1023
        const int hc = g >> 5;            // warp-uniform per i
        const int op = g & 31;            // per-lane
        const int h  = hc >> 2;
        const int c  = hc & 3;
        float acc = 0.0f;
        #pragma unroll
        for (int d = 0; d < HD; ++d)
            acc += sVb[c][h * 4 + d] * sWp[op][h * 4 + d];
        sG[hc][op] = acc;
    }
    __syncthreads();

    // ========== Phase 3: z[o] = bp[o] + sum_hc P[l][hc]*G[hc][o] ==========
    {
        float pr[NE];
        #pragma unroll
        for (int e = 0; e < NE; ++e) pr[e] = sP[l][e];
        #pragma unroll
        for (int i = 0; i < 4; ++i) {
            const int o = o0 + i;                 // warp-uniform
            float a = sbp[o];
            #pragma unroll
            for (int e = 0; e < NE; ++e) a += pr[e] * sG[e][o];  // broadcast
            sX[l][o] = a;   // sX fully consumed in phase 1
        }
    }
    __syncthreads();

    // ========== Phase 4: coalesced store ==========
    float* ob = out + (size_t)tg0 * NE;
    #pragma unroll
    for (int i = 0; i < 4; ++i) {
        const int idx = i * THR_B + tid;
        ob[idx] = sX[idx >> 5][idx & 31];
    }
}

extern "C" void kernel_launch(void* const* d_in, const int* in_sizes, int n_in,
                              void* d_out, int out_size)
{
    // metadata order: x, Wq, bq, Wk, bk, Wv, bv, Wp, bp   (Wk/bk dead)
    const float* x  = (const float*)d_in[0];
    const float* Wq = (const float*)d_in[1];
    const float* bq = (const float*)d_in[2];
    const float* Wv = (const float*)d_in[5];
    const float* bv = (const float*)d_in[6];
    const float* Wp = (const float*)d_in[7];
    const float* bp = (const float*)d_in[8];
    float* out = (float*)d_out;

    xpart_kernel<<<BB * NSLICE, 128>>>(x);
    rxtx_attn_kernel<<<NCTA_B, THR_B>>>(x, Wq, bq, Wv, bv, Wp, bp, out);
}

// round 5
// speedup vs baseline: 2.3662x; 1.0400x over previous
#include <cuda_runtime.h>
#include <cuda_bf16.h>

// Problem constants
#define BB 4
#define TT 2048
#define NE 32
#define NH 8
#define HD 4
#define NB (TT / 4)                 // 512 4-row blocks per (b,h)

#define NSLICE 64                   // xpart slices per batch (32 rows each)
#define ROWS_B 32                   // kernel B rows per CTA
#define THR_B 256                   // 8 warps: warp = head, lane = row
#define NCTA_B ((BB * TT) / ROWS_B) // 256

// g_xpart[b][s][c*32+e] = sum over slice-s rows with (row%4==c) of x[row][e]
__device__ __align__(16) float g_xpart[BB][NSLICE][128];

__device__ __forceinline__ float clip100(float v) {
    return fminf(fmaxf(v, -100.0f), 100.0f);
}

// -------- Kernel A: partial column sums of x, bucketed by (row % 4) --------
__global__ __launch_bounds__(128) void xpart_kernel(const float* __restrict__ x)
{
    const int b   = blockIdx.x >> 6;
    const int s   = blockIdx.x & 63;
    const int tid = threadIdx.x;

    const float* xs0 = x + ((size_t)b * TT + (size_t)s * 32) * NE;
    float acc = 0.0f;
    #pragma unroll
    for (int j = 0; j < 8; ++j) acc += xs0[j * 128 + tid];
    g_xpart[b][s][tid] = acc;
}

// -------- Kernel B: fused Vbar/G + q, RXTX, softmax, z = bp + P.G^T --------
// 256 threads = 8 warps (w = head) x 32 lanes (l = row).
__global__ __launch_bounds__(THR_B) void rxtx_attn_kernel(
    const float* __restrict__ x,
    const float* __restrict__ Wq, const float* __restrict__ bq,
    const float* __restrict__ Wv, const float* __restrict__ bv,
    const float* __restrict__ Wp, const float* __restrict__ bp,
    float* __restrict__ out)
{
    __shared__ __align__(16) float sWq[NE][NE];   // broadcast v4 reads (128B rows)
    __shared__ float sWv[NE][33];                  // per-lane rows, scalar
    __shared__ float sWp[NE][33];                  // per-lane rows, scalar
    __shared__ __align__(16) float sGT[NE][36];   // G transposed; broadcast v4 reads
    __shared__ float sbq[NE];
    __shared__ float sbp[NE];
    __shared__ __align__(16) float sXh8[8][128];  // xpart partials by slice-group
    __shared__ float sVb[4][NE];
    __shared__ __align__(16) float sX[ROWS_B][36]; // x rows (v4); reused for output
    __shared__ float sQ[ROWS_B][33];               // scalar access, stride 33
    __shared__ __align__(16) float sP[ROWS_B][36]; // softmax probs (v4 row reads)

    const int tid = threadIdx.x;
    const int w   = tid >> 5;           // warp = head
    const int l   = tid & 31;           // lane = row
    const int tg0 = blockIdx.x * ROWS_B;
    const int b   = tg0 >> 11;          // 64 CTAs per batch, aligned

    // ================= Phase 0: stage everything (vectorized) =================
    {
        const int ro = tid >> 3, cg = (tid & 7) * 4;    // 256 float4s cover 32x32
        const float4 wq = ((const float4*)Wq)[tid];
        *(float4*)&sWq[ro][cg] = wq;
        const float4 wv = ((const float4*)Wv)[tid];
        sWv[ro][cg + 0] = wv.x; sWv[ro][cg + 1] = wv.y;
        sWv[ro][cg + 2] = wv.z; sWv[ro][cg + 3] = wv.w;
        const float4 wp = ((const float4*)Wp)[tid];
        sWp[ro][cg + 0] = wp.x; sWp[ro][cg + 1] = wp.y;
        sWp[ro][cg + 2] = wp.z; sWp[ro][cg + 3] = wp.w;

        const float* xblk = x + (size_t)tg0 * NE;
        const float4 xv = ((const float4*)xblk)[tid];   // 256*16B = 32 rows
        *(float4*)&sX[ro][cg] = xv;
    }
    if (tid < NE)          sbq[tid]      = bq[tid];
    else if (tid < 2 * NE) sbp[tid - NE] = bp[tid - NE];

    // xpart partial reduce: warp w sums its 8 slices, float4 per lane
    {
        const int fb = l * 4;                           // float4 bucket
        float4 ps = make_float4(0.f, 0.f, 0.f, 0.f);
        #pragma unroll
        for (int s = 0; s < 8; ++s) {
            const float4 v = *(const float4*)&g_xpart[b][w * 8 + s][fb];
            ps.x += v.x; ps.y += v.y; ps.z += v.z; ps.w += v.w;
        }
        *(float4*)&sXh8[w][fb] = ps;
    }
    __syncthreads();

    // ========== Phase 1: q matvec (all warps) + Vbar (warps 0-3) ==========
    const int o0 = w * 4;
    {
        float xr[NE];
        #pragma unroll
        for (int k = 0; k < 8; ++k) {                   // v4, conflict-free
            const float4 v = *(const float4*)&sX[l][k * 4];
            xr[4*k] = v.x; xr[4*k+1] = v.y; xr[4*k+2] = v.z; xr[4*k+3] = v.w;
        }
        #pragma unroll
        for (int i = 0; i < 4; ++i) {
            const int o = o0 + i;                       // warp-uniform
            const float4* wrow = (const float4*)&sWq[o][0];
            float a = sbq[o];
            #pragma unroll
            for (int k = 0; k < 8; ++k) {
                const float4 v = wrow[k];               // broadcast LDS.128
                a += xr[4*k] * v.x + xr[4*k+1] * v.y
                   + xr[4*k+2] * v.z + xr[4*k+3] * v.w;
            }
            sQ[l][o] = clip100(a);
        }
    }
    if (w < 4) {                                        // Vbar: warp = c, lane = e/o
        const int c = w;
        float xb = 0.0f;
        #pragma unroll
        for (int sg = 0; sg < 8; ++sg) xb += sXh8[sg][c * 32 + l];
        xb *= (1.0f / (float)NB);
        float acc = bv[l];
        #pragma unroll
        for (int e = 0; e < NE; ++e)
            acc += __shfl_sync(0xffffffffu, xb, e) * sWv[l][e];
        sVb[c][l] = acc;
    }
    __syncwarp();   // RXTX only needs this warp's sQ columns

    // ========== Phase 2: RXTX + 4-way softmax (writes sP) ==========
    {
        const int blk = l & ~3;
        const int rr  = l & 3;
        const int hc  = o0;

        const float X1  = sQ[blk + 0][hc + 0], X2  = sQ[blk + 0][hc + 1],
                    X3  = sQ[blk + 0][hc + 2], X4  = sQ[blk + 0][hc + 3];
        const float X5  = sQ[blk + 1][hc + 0], X6  = sQ[blk + 1][hc + 1],
                    X7  = sQ[blk + 1][hc + 2], X8  = sQ[blk + 1][hc + 3];
        const float X9  = sQ[blk + 2][hc + 0], X10 = sQ[blk + 2][hc + 1],
                    X11 = sQ[blk + 2][hc + 2], X12 = sQ[blk + 2][hc + 3];
        const float X13 = sQ[blk + 3][hc + 0], X14 = sQ[blk + 3][hc + 1],
                    X15 = sQ[blk + 3][hc + 2], X16 = sQ[blk + 3][hc + 3];

        const float m1  = (-X2 + X3 - X4 + X8) * (X8 + X11);
        const float m2  = (X1 - X5 - X6 + X7) * (X15 + X5);
        const float m3  = (-X2 + X12) * (-X10 + X16 + X12);
        const float m4  = (X9 - X6) * (X13 + X9 - X14);
        const float m5  = (X2 + X11) * (-X6 + X15 - X7);
        const float m6  = (X6 + X11) * (X6 + X7 - X11);
        const float m7  = X11 * (X6 + X7);
        const float m8  = X2 * (-X14 - X10 + X6 - X15 + X7 + X16 + X12);
        const float m9  = X6 * (X13 + X9 - X14 - X10 + X6 + X7 - X11);
        const float m10 = (X2 - X3 + X7 + X11 + X4 - X8) * X11;
        const float m11 = (X5 + X6 - X7) * X5;
        const float m12 = (X2 - X3 + X4) * X8;
        const float m13 = (-X1 + X5 + X6 + X3 - X7 + X11) * X15;
        const float m14 = (-X1 + X5 + X6) * (X13 + X9 + X15);
        const float m15 = (X2 + X4 - X8) * (X11 + X16 + X12);
        const float m16 = (X1 - X8) * (X9 - X16);
        const float m17 = X12 * (X10 - X12);
        const float m18 = X9 * (X13 - X14);
        const float m19 = (-X2 + X3) * (-X15 + X7 + X8);
        const float m20 = (X5 + X9 - X8) * X9;
        const float m21 = X8 * (X9 - X8 + X12);
        const float m22 = (-X6 + X7) * (X5 + X7 - X11);
        const float m23 = X1 * (X13 - X5 + X16);
        const float m24 = (-X1 + X4 + X12) * X16;
        const float m25 = (X9 + X2 + X10) * X14;
        const float m26 = (X6 + X10 + X12) * X10;

        const float z1 = m7 - m11 - m12;
        const float z2 = m1 + m12 + m21;
        const float z3 = m3 + m17 - m24;
        const float z4 = m2 + m11 + m23;
        const float z5 = m5 + m7 + m8;
        const float z6 = m4 - m18 - m20;
        const float z7 = m6 - m7 - m9;
        const float z8 = m17 + m18;

        const float c01 = m2 - m5 - z1 + m13 + m19;
        const float c02 = z2 + z3 + m15 + m16;
        const float c03 = z4 - z3 - z5 - m13;
        const float c11 = m1 + m6 - z1 + m10 + m22;
        const float c12 = z2 - z6 + z7 + m10;
        const float c13 = z4 + z6 + m14 + m16;
        const float c22 = m4 - z7 - z8 + m26;
        const float c23 = m3 + z5 + z8 + m25;

        float a0, a1, a2, a3;
        if      (rr == 0) { a0 = 0.0f; a1 = c01;  a2 = c02;  a3 = c03;  }
        else if (rr == 1) { a0 = c01;  a1 = c11;  a2 = c12;  a3 = c13;  }
        else if (rr == 2) { a0 = c02;  a1 = c12;  a2 = c22;  a3 = c23;  }
        else              { a0 = c03;  a1 = c13;  a2 = c23;  a3 = 0.0f; }

        a0 = clip100(a0) * 0.5f;
        a1 = clip100(a1) * 0.5f;
        a2 = clip100(a2) * 0.5f;
        a3 = clip100(a3) * 0.5f;

        const float mx = fmaxf(fmaxf(a0, a1), fmaxf(a2, a3));
        const float e0 = __expf(a0 - mx);
        const float e1 = __expf(a1 - mx);
        const float e2 = __expf(a2 - mx);
        const float e3 = __expf(a3 - mx);
        const float inv = 1.0f / (e0 + e1 + e2 + e3);

        sP[l][hc + 0] = e0 * inv;
        sP[l][hc + 1] = e1 * inv;
        sP[l][hc + 2] = e2 * inv;
        sP[l][hc + 3] = e3 * inv;
    }
    __syncthreads();   // covers sVb (warps 0-3) and sP (all warps)

    // ========== Phase 2b: G build, stored TRANSPOSED: sGT[o'][hc] ==========
    #pragma unroll
    for (int i = 0; i < 4; ++i) {
        const int g  = i * THR_B + tid;   // 0..1023
        const int hc = g >> 5;            // warp-uniform per i
        const int op = g & 31;            // per-lane
        const int h  = hc >> 2;
        const int c  = hc & 3;
        float acc = 0.0f;
        #pragma unroll
        for (int d = 0; d < HD; ++d)
            acc += sVb[c][h * 4 + d] * sWp[op][h * 4 + d];
        sGT[op][hc] = acc;
    }
    __syncthreads();

    // ========== Phase 3: z[o] = bp[o] + sum_hc P[l][hc]*GT[o][hc] ==========
    {
        float pr[NE];
        #pragma unroll
        for (int k = 0; k < 8; ++k) {
            const float4 v = *(const float4*)&sP[l][k * 4];
            pr[4*k] = v.x; pr[4*k+1] = v.y; pr[4*k+2] = v.z; pr[4*k+3] = v.w;
        }
        #pragma unroll
        for (int i = 0; i < 4; ++i) {
            const int o = o0 + i;                        // warp-uniform
            const float4* grow = (const float4*)&sGT[o][0];
            float a = sbp[o];
            #pragma unroll
            for (int k = 0; k < 8; ++k) {
                const float4 v = grow[k];                // broadcast LDS.128
                a += pr[4*k] * v.x + pr[4*k+1] * v.y
                   + pr[4*k+2] * v.z + pr[4*k+3] * v.w;
            }
            sX[l][o] = a;     // sX fully consumed in phase 1
        }
    }
    __syncthreads();

    // ========== Phase 4: vectorized coalesced store ==========
    {
        float* ob = out + (size_t)tg0 * NE;
        const int ro = tid >> 3, cg = (tid & 7) * 4;
        ((float4*)ob)[tid] = *(const float4*)&sX[ro][cg];
    }
}

extern "C" void kernel_launch(void* const* d_in, const int* in_sizes, int n_in,
                              void* d_out, int out_size)
{
    // metadata order: x, Wq, bq, Wk, bk, Wv, bv, Wp, bp   (Wk/bk dead)
    const float* x  = (const float*)d_in[0];
    const float* Wq = (const float*)d_in[1];
    const float* bq = (const float*)d_in[2];
    const float* Wv = (const float*)d_in[5];
    const float* bv = (const float*)d_in[6];
    const float* Wp = (const float*)d_in[7];
    const float* bp = (const float*)d_in[8];
    float* out = (float*)d_out;

    xpart_kernel<<<BB * NSLICE, 128>>>(x);
    rxtx_attn_kernel<<<NCTA_B, THR_B>>>(x, Wq, bq, Wv, bv, Wp, bp, out);
}